// round 2
// baseline (speedup 1.0000x reference)
#include <cuda_runtime.h>
#include <cuda_bf16.h>

// Problem constants: B=64, S=512, H=1024, L=9
#define BB 64
#define SS 512
#define HH 1024
#define LL 9
#define NPAIR (HH / 2)      // 512 f32x2 pairs along K
#define MAIN_BLOCK 128

// Scratch (no cudaMalloc allowed) — referenced directly from device code,
// no cudaGetSymbolAddress needed.
__device__ int g_gather[BB * SS];
__device__ int g_nvalid[BB];

// ---------------------------------------------------------------------------
// Kernel A: per-batch stable compaction index (prefix scan over valid_mask)
// ---------------------------------------------------------------------------
__global__ __launch_bounds__(SS) void ner_scan_kernel(const int* __restrict__ mask)
{
    int b = blockIdx.x;
    int t = threadIdx.x;
    int m = mask[b * SS + t];

    int lane = t & 31;
    int w    = t >> 5;

    // warp inclusive scan
    int v = m;
    #pragma unroll
    for (int o = 1; o < 32; o <<= 1) {
        int n = __shfl_up_sync(0xFFFFFFFFu, v, o);
        if (lane >= o) v += n;
    }

    __shared__ int wsum[16];
    if (lane == 31) wsum[w] = v;
    __syncthreads();

    if (t < 16) {
        int s = wsum[t];
        #pragma unroll
        for (int o = 1; o < 16; o <<= 1) {
            int n = __shfl_up_sync(0x0000FFFFu, s, o);
            if (t >= o) s += n;
        }
        wsum[t] = s;
    }
    __syncthreads();

    int incl = v + (w ? wsum[w - 1] : 0);     // inclusive count of valid in [0..t]
    if (m) g_gather[b * SS + incl - 1] = t;   // stable: original order preserved
    if (t == SS - 1) g_nvalid[b] = incl;
}

// ---------------------------------------------------------------------------
// Kernel B: thread-per-row gather + GEMV (packed f32x2 FMA) + softmax(L=9)
//   row r -> batch b = r & 63, token j = r >> 6  (balances valid prefix work;
//   all 64 batches progress through token slots together, so the valid
//   region is a dense prefix of blocks and the tail exits fast)
// ---------------------------------------------------------------------------
__global__ __launch_bounds__(MAIN_BLOCK) void ner_main_kernel(
    const float* __restrict__ seq,
    const float* __restrict__ W,
    const float* __restrict__ bias,
    float* __restrict__ out)
{
    // W packed as f32x2 pairs, layout [l][pair]: Wsh[l*NPAIR+p] = (W[2p][l], W[2p+1][l])
    __shared__ unsigned long long Wsh[LL * NPAIR];   // 36,864 bytes

    int tid = threadIdx.x;
    int r = blockIdx.x * MAIN_BLOCK + tid;
    int b = r & (BB - 1);
    int j = r >> 6;

    int nv = g_nvalid[b];
    bool valid = (j < nv);

    // Skip the 36 KB W staging entirely for all-invalid (tail) blocks.
    int block_has_work = __syncthreads_or((int)valid);
    if (block_has_work) {
        for (int i = tid; i < LL * NPAIR; i += MAIN_BLOCK) {
            int l = i / NPAIR;
            int p = i - l * NPAIR;
            float lo = W[(2 * p) * LL + l];
            float hi = W[(2 * p + 1) * LL + l];
            unsigned long long u;
            asm("mov.b64 %0, {%1, %2};" : "=l"(u) : "f"(lo), "f"(hi));
            Wsh[i] = u;
        }
        __syncthreads();
    }

    float logit[LL];
    if (valid) {
        int src = g_gather[b * SS + j];
        const ulonglong2* __restrict__ xr =
            (const ulonglong2*)(seq + (((size_t)b << 9) + (size_t)src) * HH);

        unsigned long long acc[LL];
        #pragma unroll
        for (int l = 0; l < LL; l++) acc[l] = 0ull;  // packed (0.f, 0.f)

        #pragma unroll 4
        for (int it = 0; it < NPAIR / 2; it++) {     // 16 B of x per iter (2 pairs)
            ulonglong2 x = xr[it];
            #pragma unroll
            for (int l = 0; l < LL; l++)
                asm("fma.rn.f32x2 %0, %1, %2, %0;"
                    : "+l"(acc[l]) : "l"(x.x), "l"(Wsh[l * NPAIR + 2 * it]));
            #pragma unroll
            for (int l = 0; l < LL; l++)
                asm("fma.rn.f32x2 %0, %1, %2, %0;"
                    : "+l"(acc[l]) : "l"(x.y), "l"(Wsh[l * NPAIR + 2 * it + 1]));
        }

        #pragma unroll
        for (int l = 0; l < LL; l++) {
            float lo, hi;
            asm("mov.b64 {%0, %1}, %2;" : "=f"(lo), "=f"(hi) : "l"(acc[l]));
            logit[l] = lo + hi + bias[l];
        }
    } else {
        // padded tail rows: logits = 0*W + b
        #pragma unroll
        for (int l = 0; l < LL; l++) logit[l] = bias[l];
    }

    // softmax over L=9
    float m = logit[0];
    #pragma unroll
    for (int l = 1; l < LL; l++) m = fmaxf(m, logit[l]);
    float e[LL];
    float s = 0.f;
    #pragma unroll
    for (int l = 0; l < LL; l++) { e[l] = __expf(logit[l] - m); s += e[l]; }
    float inv = 1.0f / s;

    float* __restrict__ o = out + ((size_t)b * SS + (size_t)j) * LL;
    #pragma unroll
    for (int l = 0; l < LL; l++) o[l] = e[l] * inv;
}

// ---------------------------------------------------------------------------
// Launch: inputs per metadata order:
//   d_in[0] sequence_output f32 [64,512,1024]
//   d_in[1] valid_mask      i32 [64,512]
//   d_in[2] W               f32 [1024,9]
//   d_in[3] b               f32 [9]
// output f32 [64,512,9]
// ---------------------------------------------------------------------------
extern "C" void kernel_launch(void* const* d_in, const int* in_sizes, int n_in,
                              void* d_out, int out_size)
{
    const float* seq  = (const float*)d_in[0];
    const int*   mask = (const int*)  d_in[1];
    const float* W    = (const float*)d_in[2];
    const float* bias = (const float*)d_in[3];
    float*       out  = (float*)d_out;

    ner_scan_kernel<<<BB, SS>>>(mask);

    int rows = BB * SS;
    ner_main_kernel<<<rows / MAIN_BLOCK, MAIN_BLOCK>>>(seq, W, bias, out);
}

// round 3
// speedup vs baseline: 1.2764x; 1.2764x over previous
#include <cuda_runtime.h>
#include <cuda_bf16.h>

// Problem constants: B=64, S=512, H=1024, L=9
#define BB 64
#define SS 512
#define HH 1024
#define LL 9
#define NPAIR (HH / 2)          // 512 f32x2 pairs along K
#define NCHUNK 4                // K split into 4 chunks of 256 floats
#define CPAIR (NPAIR / NCHUNK)  // 128 pairs per chunk
#define CPAD (CPAIR + 1)        // +1 pair pad -> chunk regions land on distinct banks
#define MAIN_BLOCK 256

// Scratch (no cudaMalloc allowed)
__device__ int g_gather[BB * SS];
__device__ int g_nvalid[BB];

// ---------------------------------------------------------------------------
// Kernel A: per-batch stable compaction index (prefix scan over valid_mask)
// ---------------------------------------------------------------------------
__global__ __launch_bounds__(SS) void ner_scan_kernel(const int* __restrict__ mask)
{
    int b = blockIdx.x;
    int t = threadIdx.x;
    int m = mask[b * SS + t];

    int lane = t & 31;
    int w    = t >> 5;

    int v = m;
    #pragma unroll
    for (int o = 1; o < 32; o <<= 1) {
        int n = __shfl_up_sync(0xFFFFFFFFu, v, o);
        if (lane >= o) v += n;
    }

    __shared__ int wsum[16];
    if (lane == 31) wsum[w] = v;
    __syncthreads();

    if (t < 16) {
        int s = wsum[t];
        #pragma unroll
        for (int o = 1; o < 16; o <<= 1) {
            int n = __shfl_up_sync(0x0000FFFFu, s, o);
            if (t >= o) s += n;
        }
        wsum[t] = s;
    }
    __syncthreads();

    int incl = v + (w ? wsum[w - 1] : 0);
    if (m) g_gather[b * SS + incl - 1] = t;      // stable compaction
    if (t == SS - 1) g_nvalid[b] = incl;
}

// ---------------------------------------------------------------------------
// Kernel B: warp handles 16 rows (8 lane-slots x 2 rows), K split 4-way across
// lane groups (c = lane>>3). Packed f32x2 FMA; W staged in SMEM, each W pair
// loaded once per thread and reused for 2 rows. Chunk partials reduced with
// two shfl_xor rounds; lanes c==0 do softmax + store.
// ---------------------------------------------------------------------------
__global__ __launch_bounds__(MAIN_BLOCK) void ner_main_kernel(
    const float* __restrict__ seq,
    const float* __restrict__ W,
    const float* __restrict__ bias,
    float* __restrict__ out)
{
    // Wsh[(l*4 + c)*CPAD + p] = (W[2*(c*128+p)][l], W[2*(c*128+p)+1][l])
    __shared__ unsigned long long Wsh[LL * NCHUNK * CPAD];   // 37,152 bytes

    int tid  = threadIdx.x;
    int lane = tid & 31;
    int rp   = lane & 7;       // row-pair slot within warp
    int c    = lane >> 3;      // K-chunk 0..3

    int gw     = blockIdx.x * (MAIN_BLOCK / 32) + (tid >> 5);
    int base_r = gw * 16;
    int rA = base_r + rp * 2;
    int rB = rA + 1;
    int bA = rA & (BB - 1);
    int bB = bA + 1;           // never wraps (rA is even, <= 62 within group)
    int j  = rA >> 6;          // same token slot for the whole warp

    int nvA = g_nvalid[bA];
    int nvB = g_nvalid[bB];
    bool validA = (j < nvA);
    bool validB = (j < nvB);

    // Skip 37 KB W staging for all-invalid (tail) blocks
    int block_has_work = __syncthreads_or((int)(validA || validB));
    if (block_has_work) {
        for (int i = tid; i < LL * NCHUNK * CPAIR; i += MAIN_BLOCK) {
            int l   = i >> 9;              // / 512
            int rem = i & 511;
            int cc  = rem >> 7;            // / 128
            int p   = rem & 127;
            int kf  = (cc * CPAIR + p) * 2;
            float lo = W[kf * LL + l];
            float hi = W[(kf + 1) * LL + l];
            unsigned long long u;
            asm("mov.b64 %0, {%1, %2};" : "=l"(u) : "f"(lo), "f"(hi));
            Wsh[(l * NCHUNK + cc) * CPAD + p] = u;
        }
        __syncthreads();
    }

    unsigned long long accA[LL], accB[LL];
    #pragma unroll
    for (int l = 0; l < LL; l++) { accA[l] = 0ull; accB[l] = 0ull; }

    bool warp_any = __any_sync(0xFFFFFFFFu, validA || validB);
    if (warp_any) {
        // Clamp src for invalid rows (uniform execution; result discarded)
        int srcA = validA ? g_gather[bA * SS + j] : 0;
        int srcB = validB ? g_gather[bB * SS + j] : 0;
        const ulonglong2* __restrict__ xrA = (const ulonglong2*)
            (seq + (((size_t)bA << 9) + (size_t)srcA) * HH + c * (HH / NCHUNK));
        const ulonglong2* __restrict__ xrB = (const ulonglong2*)
            (seq + (((size_t)bB << 9) + (size_t)srcB) * HH + c * (HH / NCHUNK));

        int wb[LL];
        #pragma unroll
        for (int l = 0; l < LL; l++) wb[l] = (l * NCHUNK + c) * CPAD;

        #pragma unroll 4
        for (int it = 0; it < CPAIR / 2; it++) {   // 64 iters, 16B per row per iter
            ulonglong2 xA = xrA[it];
            ulonglong2 xB = xrB[it];
            #pragma unroll
            for (int l = 0; l < LL; l++) {
                unsigned long long w0 = Wsh[wb[l] + 2 * it];
                unsigned long long w1 = Wsh[wb[l] + 2 * it + 1];
                asm("fma.rn.f32x2 %0, %1, %2, %0;" : "+l"(accA[l]) : "l"(xA.x), "l"(w0));
                asm("fma.rn.f32x2 %0, %1, %2, %0;" : "+l"(accA[l]) : "l"(xA.y), "l"(w1));
                asm("fma.rn.f32x2 %0, %1, %2, %0;" : "+l"(accB[l]) : "l"(xB.x), "l"(w0));
                asm("fma.rn.f32x2 %0, %1, %2, %0;" : "+l"(accB[l]) : "l"(xB.y), "l"(w1));
            }
        }
    }

    // Unpack and reduce the 4 K-chunks (lanes rp, rp+8, rp+16, rp+24)
    float sumA[LL], sumB[LL];
    #pragma unroll
    for (int l = 0; l < LL; l++) {
        float lo, hi;
        asm("mov.b64 {%0, %1}, %2;" : "=f"(lo), "=f"(hi) : "l"(accA[l]));
        sumA[l] = lo + hi;
        asm("mov.b64 {%0, %1}, %2;" : "=f"(lo), "=f"(hi) : "l"(accB[l]));
        sumB[l] = lo + hi;
    }
    #pragma unroll
    for (int l = 0; l < LL; l++) {
        sumA[l] += __shfl_xor_sync(0xFFFFFFFFu, sumA[l], 8);
        sumA[l] += __shfl_xor_sync(0xFFFFFFFFu, sumA[l], 16);
        sumB[l] += __shfl_xor_sync(0xFFFFFFFFu, sumB[l], 8);
        sumB[l] += __shfl_xor_sync(0xFFFFFFFFu, sumB[l], 16);
    }

    if (c == 0) {
        float bi[LL];
        #pragma unroll
        for (int l = 0; l < LL; l++) bi[l] = bias[l];

        // ---- row A ----
        {
            float logit[LL];
            #pragma unroll
            for (int l = 0; l < LL; l++) logit[l] = validA ? (sumA[l] + bi[l]) : bi[l];
            float m = logit[0];
            #pragma unroll
            for (int l = 1; l < LL; l++) m = fmaxf(m, logit[l]);
            float e[LL], s = 0.f;
            #pragma unroll
            for (int l = 0; l < LL; l++) { e[l] = __expf(logit[l] - m); s += e[l]; }
            float inv = 1.0f / s;
            float* __restrict__ o = out + ((size_t)bA * SS + (size_t)j) * LL;
            #pragma unroll
            for (int l = 0; l < LL; l++) o[l] = e[l] * inv;
        }
        // ---- row B ----
        {
            float logit[LL];
            #pragma unroll
            for (int l = 0; l < LL; l++) logit[l] = validB ? (sumB[l] + bi[l]) : bi[l];
            float m = logit[0];
            #pragma unroll
            for (int l = 1; l < LL; l++) m = fmaxf(m, logit[l]);
            float e[LL], s = 0.f;
            #pragma unroll
            for (int l = 0; l < LL; l++) { e[l] = __expf(logit[l] - m); s += e[l]; }
            float inv = 1.0f / s;
            float* __restrict__ o = out + ((size_t)bB * SS + (size_t)j) * LL;
            #pragma unroll
            for (int l = 0; l < LL; l++) o[l] = e[l] * inv;
        }
    }
}

// ---------------------------------------------------------------------------
// Launch. Inputs: [0] seq f32 [64,512,1024], [1] mask i32 [64,512],
//                 [2] W f32 [1024,9], [3] b f32 [9]; out f32 [64,512,9]
// ---------------------------------------------------------------------------
extern "C" void kernel_launch(void* const* d_in, const int* in_sizes, int n_in,
                              void* d_out, int out_size)
{
    const float* seq  = (const float*)d_in[0];
    const int*   mask = (const int*)  d_in[1];
    const float* W    = (const float*)d_in[2];
    const float* bias = (const float*)d_in[3];
    float*       out  = (float*)d_out;

    ner_scan_kernel<<<BB, SS>>>(mask);

    // 32768 row slots, 2 rows/thread, 4 K-chunks -> 65536 threads
    int total_threads = (BB * SS / 2) * NCHUNK;
    ner_main_kernel<<<total_threads / MAIN_BLOCK, MAIN_BLOCK>>>(seq, W, bias, out);
}